// round 1
// baseline (speedup 1.0000x reference)
#include <cuda_runtime.h>
#include <math.h>

#define BB 16
#define CC 256
#define HH 96
#define WW 96
#define GG 16
#define CPG (CC/GG)          // 16
#define HWP (HH*WW)          // 9216
#define NTOT (BB*CC*HWP)     // 37748736
#define GROUPN (CPG*HWP)     // 147456

// Scratch (device globals: no allocations allowed)
__device__ float g_buf0[NTOT];
__device__ float g_buf1[NTOT];
__device__ float g_buf2[NTOT];
__device__ float g_mean[BB*GG];
__device__ float g_rstd[BB*GG];

__device__ __forceinline__ float sigf(float x){ return 1.0f/(1.0f+expf(-x)); }

// ---------------------------------------------------------------------------
// GEMM: Y[b][o][p] = sum_c A[o][c] * X[b][c][p]   (A: [256][256] row-major)
// EPI=0: plain store. EPI=1: sigmoid(v + bias[o]).
// Tile 128x128, BK=8, 256 threads, 8x8 microtile.
// ---------------------------------------------------------------------------
template<int EPI>
__global__ __launch_bounds__(256) void gemm_kernel(
    const float* __restrict__ A, const float* __restrict__ X,
    float* __restrict__ Y, const float* __restrict__ bias)
{
    const int BM = 128, BN = 128, BK = 8;
    __shared__ __align__(16) float As[BK][BM];
    __shared__ __align__(16) float Bs[BK][BN];

    const int b   = blockIdx.z;
    const int om0 = blockIdx.y * BM;   // output channel tile
    const int pn0 = blockIdx.x * BN;   // pixel tile
    const int tid = threadIdx.x;
    const int tr  = tid >> 4;          // 0..15
    const int tc  = tid & 15;          // 0..15

    const float* Xb = X + (size_t)b * CC * HWP;
    float* Yb       = Y + (size_t)b * CC * HWP;

    float acc[8][8];
#pragma unroll
    for (int i = 0; i < 8; i++)
#pragma unroll
        for (int j = 0; j < 8; j++) acc[i][j] = 0.f;

    for (int k0 = 0; k0 < CC; k0 += BK) {
        // Load A tile: 128 rows x 8 k, 4 floats/thread
        {
            int row = tid >> 1;
            int kc  = (tid & 1) * 4;
            float4 v = *(const float4*)&A[(size_t)(om0 + row) * CC + k0 + kc];
            As[kc+0][row] = v.x; As[kc+1][row] = v.y;
            As[kc+2][row] = v.z; As[kc+3][row] = v.w;
        }
        // Load B tile: 8 k-rows x 128 pixels, 4 floats/thread (coalesced)
        {
            int kr = tid >> 5;
            int pc = (tid & 31) * 4;
            float4 v = *(const float4*)&Xb[(size_t)(k0 + kr) * HWP + pn0 + pc];
            *(float4*)&Bs[kr][pc] = v;
        }
        __syncthreads();

#pragma unroll
        for (int k = 0; k < BK; k++) {
            float4 a0 = *(const float4*)&As[k][tr*8];
            float4 a1 = *(const float4*)&As[k][tr*8+4];
            float4 b0 = *(const float4*)&Bs[k][tc*8];
            float4 b1 = *(const float4*)&Bs[k][tc*8+4];
            float av[8] = {a0.x,a0.y,a0.z,a0.w,a1.x,a1.y,a1.z,a1.w};
            float bv[8] = {b0.x,b0.y,b0.z,b0.w,b1.x,b1.y,b1.z,b1.w};
#pragma unroll
            for (int i = 0; i < 8; i++)
#pragma unroll
                for (int j = 0; j < 8; j++)
                    acc[i][j] = fmaf(av[i], bv[j], acc[i][j]);
        }
        __syncthreads();
    }

#pragma unroll
    for (int i = 0; i < 8; i++) {
        int o = om0 + tr*8 + i;
        float bo = (EPI == 1) ? bias[o] : 0.f;
        size_t rowoff = (size_t)o * HWP + pn0 + tc*8;
#pragma unroll
        for (int j = 0; j < 8; j += 4) {
            float4 v;
            v.x = acc[i][j+0]; v.y = acc[i][j+1];
            v.z = acc[i][j+2]; v.w = acc[i][j+3];
            if (EPI == 1) {
                v.x = sigf(v.x + bo); v.y = sigf(v.y + bo);
                v.z = sigf(v.z + bo); v.w = sigf(v.w + bo);
            }
            *(float4*)&Yb[rowoff + j] = v;
        }
    }
}

// ---------------------------------------------------------------------------
// Per-(b,g) mean/rstd over contiguous GROUPN floats. 256 blocks of 256.
// ---------------------------------------------------------------------------
__global__ __launch_bounds__(256) void stats_kernel(const float* __restrict__ in)
{
    int bg = blockIdx.x;
    const float4* p = (const float4*)(in + (size_t)bg * GROUPN);
    float s = 0.f, s2 = 0.f;
    for (int i = threadIdx.x; i < GROUPN/4; i += 256) {
        float4 v = p[i];
        s  += v.x + v.y + v.z + v.w;
        s2 += v.x*v.x + v.y*v.y + v.z*v.z + v.w*v.w;
    }
    __shared__ float sh[256], sh2[256];
    sh[threadIdx.x] = s; sh2[threadIdx.x] = s2;
    __syncthreads();
    for (int off = 128; off > 0; off >>= 1) {
        if (threadIdx.x < off) {
            sh[threadIdx.x]  += sh[threadIdx.x + off];
            sh2[threadIdx.x] += sh2[threadIdx.x + off];
        }
        __syncthreads();
    }
    if (threadIdx.x == 0) {
        float mean = sh[0] / (float)GROUPN;
        float var  = sh2[0] / (float)GROUPN - mean*mean;
        g_mean[bg] = mean;
        g_rstd[bg] = rsqrtf(var + 1e-5f);
    }
}

// ---------------------------------------------------------------------------
// Apply group norm + SiLU (vectorized float4)
// ---------------------------------------------------------------------------
__global__ __launch_bounds__(256) void gn_silu_kernel(
    const float* __restrict__ in, float* __restrict__ out,
    const float* __restrict__ gw, const float* __restrict__ gb)
{
    int i4 = blockIdx.x * 256 + threadIdx.x;
    if (i4 >= NTOT/4) return;
    size_t idx = (size_t)i4 * 4;
    int c = (int)((idx / HWP) % CC);
    int b = (int)(idx / ((size_t)CC * HWP));
    int bg = b * GG + c / CPG;
    float m = g_mean[bg], rs = g_rstd[bg];
    float sw = gw[c] * rs;
    float sb = gb[c] - m * sw;
    float4 v = *(const float4*)&in[idx];
    float y;
    y = fmaf(v.x, sw, sb); v.x = y * sigf(y);
    y = fmaf(v.y, sw, sb); v.y = y * sigf(y);
    y = fmaf(v.z, sw, sb); v.z = y * sigf(y);
    y = fmaf(v.w, sw, sb); v.w = y * sigf(y);
    *(float4*)&out[idx] = v;
}

// ---------------------------------------------------------------------------
// W-direction scans (lr forward + rl backward). One thread per (b,c,h) row.
// out = lr + rl
// ---------------------------------------------------------------------------
__global__ __launch_bounds__(256) void scanW_kernel(
    const float* __restrict__ xp, float* __restrict__ out,
    const float* __restrict__ a_p, const float* __restrict__ b_p,
    const float* __restrict__ c_p, const float* __restrict__ d_p)
{
    int r = blockIdx.x * 256 + threadIdx.x;
    if (r >= BB*CC*HH) return;
    int c = (r / HH) % CC;
    float a0 = sigf(a_p[c]),      b0 = b_p[c],      c0 = c_p[c],      d0 = d_p[c];
    float a1 = sigf(a_p[CC + c]), b1 = b_p[CC + c], c1 = c_p[CC + c], d1 = d_p[CC + c];
    size_t base = (size_t)r * WW;

    float h = 0.f;
    for (int i0 = 0; i0 < WW; i0 += 4) {
        float4 x = *(const float4*)&xp[base + i0];
        float4 y;
        h = fmaf(a0, h, b0 * x.x); y.x = fmaf(c0, h, d0 * x.x);
        h = fmaf(a0, h, b0 * x.y); y.y = fmaf(c0, h, d0 * x.y);
        h = fmaf(a0, h, b0 * x.z); y.z = fmaf(c0, h, d0 * x.z);
        h = fmaf(a0, h, b0 * x.w); y.w = fmaf(c0, h, d0 * x.w);
        *(float4*)&out[base + i0] = y;
    }
    h = 0.f;
    for (int i0 = WW - 4; i0 >= 0; i0 -= 4) {
        float4 x = *(const float4*)&xp[base + i0];
        float4 o = *(float4*)&out[base + i0];
        h = fmaf(a1, h, b1 * x.w); o.w += fmaf(c1, h, d1 * x.w);
        h = fmaf(a1, h, b1 * x.z); o.z += fmaf(c1, h, d1 * x.z);
        h = fmaf(a1, h, b1 * x.y); o.y += fmaf(c1, h, d1 * x.y);
        h = fmaf(a1, h, b1 * x.x); o.x += fmaf(c1, h, d1 * x.x);
        *(float4*)&out[base + i0] = o;
    }
}

// ---------------------------------------------------------------------------
// H-direction scans (tb forward + bt backward) + final combine with gate.
// One thread handles 4 adjacent columns (float4). acc holds lr+rl on entry;
// on exit acc = 0.25*(lr+rl+tb+bt)*gate.
// ---------------------------------------------------------------------------
__global__ __launch_bounds__(256) void scanH_kernel(
    const float* __restrict__ xp, const float* __restrict__ gate,
    float* __restrict__ acc,
    const float* __restrict__ a_p, const float* __restrict__ b_p,
    const float* __restrict__ c_p, const float* __restrict__ d_p)
{
    int t = blockIdx.x * 256 + threadIdx.x;
    if (t >= BB*CC*(WW/4)) return;
    int wq = t % (WW/4);
    int bc = t / (WW/4);
    int c  = bc % CC;
    float a2 = sigf(a_p[2*CC + c]), b2 = b_p[2*CC + c], c2 = c_p[2*CC + c], d2 = d_p[2*CC + c];
    float a3 = sigf(a_p[3*CC + c]), b3 = b_p[3*CC + c], c3 = c_p[3*CC + c], d3 = d_p[3*CC + c];
    size_t base = (size_t)bc * HWP + wq * 4;

    float4 h = make_float4(0.f, 0.f, 0.f, 0.f);
    for (int j = 0; j < HH; j++) {
        size_t off = base + (size_t)j * WW;
        float4 x = *(const float4*)&xp[off];
        float4 o = *(float4*)&acc[off];
        h.x = fmaf(a2, h.x, b2 * x.x); o.x += fmaf(c2, h.x, d2 * x.x);
        h.y = fmaf(a2, h.y, b2 * x.y); o.y += fmaf(c2, h.y, d2 * x.y);
        h.z = fmaf(a2, h.z, b2 * x.z); o.z += fmaf(c2, h.z, d2 * x.z);
        h.w = fmaf(a2, h.w, b2 * x.w); o.w += fmaf(c2, h.w, d2 * x.w);
        *(float4*)&acc[off] = o;
    }
    h = make_float4(0.f, 0.f, 0.f, 0.f);
    for (int j = HH - 1; j >= 0; j--) {
        size_t off = base + (size_t)j * WW;
        float4 x = *(const float4*)&xp[off];
        float4 o = *(float4*)&acc[off];
        float4 g = *(const float4*)&gate[off];
        h.x = fmaf(a3, h.x, b3 * x.x); o.x = 0.25f * (o.x + fmaf(c3, h.x, d3 * x.x)) * g.x;
        h.y = fmaf(a3, h.y, b3 * x.y); o.y = 0.25f * (o.y + fmaf(c3, h.y, d3 * x.y)) * g.y;
        h.z = fmaf(a3, h.z, b3 * x.z); o.z = 0.25f * (o.z + fmaf(c3, h.z, d3 * x.z)) * g.z;
        h.w = fmaf(a3, h.w, b3 * x.w); o.w = 0.25f * (o.w + fmaf(c3, h.w, d3 * x.w)) * g.w;
        *(float4*)&acc[off] = o;
    }
}

// ---------------------------------------------------------------------------
// Depthwise 3x3 conv, SAME zero padding. One thread per output pixel.
// dw_w layout: [C][1][3][3] -> wt[c*9 + kh*3 + kw], cross-correlation (no flip)
// ---------------------------------------------------------------------------
__global__ __launch_bounds__(256) void dw_kernel(
    const float* __restrict__ in, const float* __restrict__ wt,
    float* __restrict__ out)
{
    int idx = blockIdx.x * 256 + threadIdx.x;
    if (idx >= NTOT) return;
    int w = idx % WW;
    int h = (idx / WW) % HH;
    int c = (idx / HWP) % CC;
    const float* pk = wt + c * 9;
    float k0 = pk[0], k1 = pk[1], k2 = pk[2];
    float k3 = pk[3], k4 = pk[4], k5 = pk[5];
    float k6 = pk[6], k7 = pk[7], k8 = pk[8];
    const float* pl = in + (size_t)(idx / HWP) * HWP;
    float s = 0.f;
    if (h > 0) {
        const float* r = pl + (size_t)(h-1) * WW;
        if (w > 0)    s = fmaf(r[w-1], k0, s);
                      s = fmaf(r[w],   k1, s);
        if (w < WW-1) s = fmaf(r[w+1], k2, s);
    }
    {
        const float* r = pl + (size_t)h * WW;
        if (w > 0)    s = fmaf(r[w-1], k3, s);
                      s = fmaf(r[w],   k4, s);
        if (w < WW-1) s = fmaf(r[w+1], k5, s);
    }
    if (h < HH-1) {
        const float* r = pl + (size_t)(h+1) * WW;
        if (w > 0)    s = fmaf(r[w-1], k6, s);
                      s = fmaf(r[w],   k7, s);
        if (w < WW-1) s = fmaf(r[w+1], k8, s);
    }
    out[idx] = s;
}

// ---------------------------------------------------------------------------
extern "C" void kernel_launch(void* const* d_in, const int* in_sizes, int n_in,
                              void* d_out, int out_size)
{
    const float* x      = (const float*)d_in[0];
    const float* in_w   = (const float*)d_in[1];
    const float* gn1_w  = (const float*)d_in[2];
    const float* gn1_b  = (const float*)d_in[3];
    const float* a_p    = (const float*)d_in[4];
    const float* b_p    = (const float*)d_in[5];
    const float* c_p    = (const float*)d_in[6];
    const float* d_p    = (const float*)d_in[7];
    const float* gate_w = (const float*)d_in[8];
    const float* gate_b = (const float*)d_in[9];
    const float* dw_w   = (const float*)d_in[10];
    const float* pw_w   = (const float*)d_in[11];
    const float* gn2_w  = (const float*)d_in[12];
    const float* gn2_b  = (const float*)d_in[13];
    float* out = (float*)d_out;

    float *buf0, *buf1, *buf2;
    cudaGetSymbolAddress((void**)&buf0, g_buf0);
    cudaGetSymbolAddress((void**)&buf1, g_buf1);
    cudaGetSymbolAddress((void**)&buf2, g_buf2);

    dim3 ggrid(HWP/128, CC/128, BB);   // (72, 2, 16)
    int elem4_blocks = (NTOT/4 + 255) / 256;     // 36864
    int scanW_blocks = (BB*CC*HH + 255) / 256;   // 1536
    int scanH_blocks = (BB*CC*(WW/4) + 255) / 256; // 384
    int dw_blocks    = (NTOT + 255) / 256;       // 147456

    // 1. xp_raw = in_w @ x
    gemm_kernel<0><<<ggrid, 256>>>(in_w, x, buf0, nullptr);
    // 2. gn1 stats
    stats_kernel<<<BB*GG, 256>>>(buf0);
    // 3. xp = silu(gn1(xp_raw))
    gn_silu_kernel<<<elem4_blocks, 256>>>(buf0, buf1, gn1_w, gn1_b);
    // 4. gate = sigmoid(gate_w @ xp + gate_b)
    gemm_kernel<1><<<ggrid, 256>>>(gate_w, buf1, buf0, gate_b);
    // 5. buf2 = lr + rl
    scanW_kernel<<<scanW_blocks, 256>>>(buf1, buf2, a_p, b_p, c_p, d_p);
    // 6. buf2 = 0.25*(lr+rl+tb+bt)*gate
    scanH_kernel<<<scanH_blocks, 256>>>(buf1, buf0, buf2, a_p, b_p, c_p, d_p);
    // 7. depthwise 3x3
    dw_kernel<<<dw_blocks, 256>>>(buf2, dw_w, buf1);
    // 8. out_raw = pw_w @ dw
    gemm_kernel<0><<<ggrid, 256>>>(pw_w, buf1, buf0, nullptr);
    // 9. gn2 stats
    stats_kernel<<<BB*GG, 256>>>(buf0);
    // 10. out = silu(gn2(out_raw))
    gn_silu_kernel<<<elem4_blocks, 256>>>(buf0, out, gn2_w, gn2_b);
}

// round 3
// speedup vs baseline: 1.2898x; 1.2898x over previous
#include <cuda_runtime.h>
#include <math.h>
#include <stdint.h>

#define BB 16
#define CC 256
#define HH 96
#define WW 96
#define GG 16
#define CPG (CC/GG)          // 16
#define HWP (HH*WW)          // 9216
#define NTOT (BB*CC*HWP)     // 37748736
#define GROUPN (CPG*HWP)     // 147456

// Scratch (device globals: no allocations allowed)
__device__ float g_buf0[NTOT];
__device__ float g_buf1[NTOT];
__device__ float g_buf2[NTOT];
__device__ float g_mean[BB*GG];
__device__ float g_rstd[BB*GG];

__device__ __forceinline__ float sigf(float x){ return 1.0f/(1.0f+expf(-x)); }

// ---------------------------------------------------------------------------
// Tensor-core GEMM (3xTF32 split precision, ~fp32 accuracy):
//   Y[b][o][p] = sum_c A[o][c] * X[b][c][p]
// Block tile 128x128, BK=16, 256 threads = 8 warps (2 M x 4 N), each warp
// 64x32 via 4x4 grid of m16n8k8 mma. EPI=0: plain, EPI=1: sigmoid(v+bias[o]).
// ---------------------------------------------------------------------------
__device__ __forceinline__ void mma_tf32(float c[4], const uint32_t a[4], const uint32_t b[2]) {
    asm volatile(
        "mma.sync.aligned.m16n8k8.row.col.f32.tf32.tf32.f32 "
        "{%0,%1,%2,%3}, {%4,%5,%6,%7}, {%8,%9}, {%0,%1,%2,%3};\n"
        : "+f"(c[0]), "+f"(c[1]), "+f"(c[2]), "+f"(c[3])
        : "r"(a[0]), "r"(a[1]), "r"(a[2]), "r"(a[3]), "r"(b[0]), "r"(b[1]));
}

__device__ __forceinline__ void split_tf32(float x, uint32_t& hi, uint32_t& lo) {
    uint32_t xb = __float_as_uint(x) & 0xffffe000u;   // truncate to tf32
    hi = xb;
    lo = __float_as_uint(x - __uint_as_float(xb));    // residual (exact in fp32)
}

template<int EPI>
__global__ __launch_bounds__(256) void gemm_tc(
    const float* __restrict__ A, const float* __restrict__ X,
    float* __restrict__ Y, const float* __restrict__ bias)
{
    const int BK = 16;
    const int LD = 136;                 // row pitch (floats): conflict-free frag loads
    __shared__ __align__(16) float As[BK * LD];   // [k][m]
    __shared__ __align__(16) float Bs[BK * LD];   // [k][n]

    const int b   = blockIdx.z;
    const int om0 = blockIdx.y * 128;
    const int pn0 = blockIdx.x * 128;
    const int tid = threadIdx.x;
    const int lane = tid & 31;
    const int warp = tid >> 5;
    const int wm = (warp >> 2) * 64;    // warp M offset (0 or 64)
    const int wn = (warp & 3) * 32;     // warp N offset
    const int r  = lane >> 2;           // 0..7
    const int q  = lane & 3;            // 0..3

    const float* Xb = X + (size_t)b * CC * HWP;
    float* Yb       = Y + (size_t)b * CC * HWP;

    float acc[4][4][4];
#pragma unroll
    for (int mi = 0; mi < 4; mi++)
#pragma unroll
        for (int ni = 0; ni < 4; ni++)
#pragma unroll
            for (int k = 0; k < 4; k++) acc[mi][ni][k] = 0.f;

    // Global load addressing (constant per thread)
    const int a_row = tid >> 1;             // 0..127
    const int a_kc  = (tid & 1) * 8;        // 0 or 8
    const int b_kr  = tid >> 4;             // 0..15
    const int b_pc  = (tid & 15) * 8;       // 0..120

    for (int k0 = 0; k0 < CC; k0 += BK) {
        // A tile: 128 rows x 16 k
        {
            const float* ap = A + (size_t)(om0 + a_row) * CC + k0 + a_kc;
            float4 v0 = *(const float4*)ap;
            float4 v1 = *(const float4*)(ap + 4);
            As[(a_kc+0)*LD + a_row] = v0.x; As[(a_kc+1)*LD + a_row] = v0.y;
            As[(a_kc+2)*LD + a_row] = v0.z; As[(a_kc+3)*LD + a_row] = v0.w;
            As[(a_kc+4)*LD + a_row] = v1.x; As[(a_kc+5)*LD + a_row] = v1.y;
            As[(a_kc+6)*LD + a_row] = v1.z; As[(a_kc+7)*LD + a_row] = v1.w;
        }
        // B tile: 16 k-rows x 128 pixels (coalesced, aligned: LD*4=544 is 16B mult)
        {
            const float* bp = Xb + (size_t)(k0 + b_kr) * HWP + pn0 + b_pc;
            *(float4*)&Bs[b_kr*LD + b_pc]     = *(const float4*)bp;
            *(float4*)&Bs[b_kr*LD + b_pc + 4] = *(const float4*)(bp + 4);
        }
        __syncthreads();

#pragma unroll
        for (int ks = 0; ks < BK; ks += 8) {
            // A fragments (hi/lo) for 4 m-tiles
            uint32_t ah[4][4], al[4][4];
#pragma unroll
            for (int mi = 0; mi < 4; mi++) {
                int m0 = wm + mi*16 + r;
                split_tf32(As[(ks+q  )*LD + m0    ], ah[mi][0], al[mi][0]);
                split_tf32(As[(ks+q  )*LD + m0 + 8], ah[mi][1], al[mi][1]);
                split_tf32(As[(ks+q+4)*LD + m0    ], ah[mi][2], al[mi][2]);
                split_tf32(As[(ks+q+4)*LD + m0 + 8], ah[mi][3], al[mi][3]);
            }
#pragma unroll
            for (int ni = 0; ni < 4; ni++) {
                int n0 = wn + ni*8 + r;
                uint32_t bh[2], bl[2];
                split_tf32(Bs[(ks+q  )*LD + n0], bh[0], bl[0]);
                split_tf32(Bs[(ks+q+4)*LD + n0], bh[1], bl[1]);
#pragma unroll
                for (int mi = 0; mi < 4; mi++) {
                    mma_tf32(acc[mi][ni], ah[mi], bh);   // hi*hi
                    mma_tf32(acc[mi][ni], al[mi], bh);   // lo*hi
                    mma_tf32(acc[mi][ni], ah[mi], bl);   // hi*lo
                }
            }
        }
        __syncthreads();
    }

    // Epilogue. c0:(r, 2q) c1:(r, 2q+1) c2:(r+8, 2q) c3:(r+8, 2q+1)
#pragma unroll
    for (int mi = 0; mi < 4; mi++) {
        int o0 = om0 + wm + mi*16 + r;
        float bo0 = 0.f, bo1 = 0.f;
        if (EPI == 1) { bo0 = bias[o0]; bo1 = bias[o0 + 8]; }
#pragma unroll
        for (int ni = 0; ni < 4; ni++) {
            int p = pn0 + wn + ni*8 + 2*q;
            float2 v0, v1;
            v0.x = acc[mi][ni][0]; v0.y = acc[mi][ni][1];
            v1.x = acc[mi][ni][2]; v1.y = acc[mi][ni][3];
            if (EPI == 1) {
                v0.x = sigf(v0.x + bo0); v0.y = sigf(v0.y + bo0);
                v1.x = sigf(v1.x + bo1); v1.y = sigf(v1.y + bo1);
            }
            *(float2*)&Yb[(size_t)o0 * HWP + p]       = v0;
            *(float2*)&Yb[(size_t)(o0+8) * HWP + p]   = v1;
        }
    }
}

// ---------------------------------------------------------------------------
// Per-(b,g) mean/rstd over contiguous GROUPN floats. 256 blocks of 256.
// ---------------------------------------------------------------------------
__global__ __launch_bounds__(256) void stats_kernel(const float* __restrict__ in)
{
    int bg = blockIdx.x;
    const float4* p = (const float4*)(in + (size_t)bg * GROUPN);
    float s = 0.f, s2 = 0.f;
    for (int i = threadIdx.x; i < GROUPN/4; i += 256) {
        float4 v = p[i];
        s  += v.x + v.y + v.z + v.w;
        s2 += v.x*v.x + v.y*v.y + v.z*v.z + v.w*v.w;
    }
    __shared__ float sh[256], sh2[256];
    sh[threadIdx.x] = s; sh2[threadIdx.x] = s2;
    __syncthreads();
    for (int off = 128; off > 0; off >>= 1) {
        if (threadIdx.x < off) {
            sh[threadIdx.x]  += sh[threadIdx.x + off];
            sh2[threadIdx.x] += sh2[threadIdx.x + off];
        }
        __syncthreads();
    }
    if (threadIdx.x == 0) {
        float mean = sh[0] / (float)GROUPN;
        float var  = sh2[0] / (float)GROUPN - mean*mean;
        g_mean[bg] = mean;
        g_rstd[bg] = rsqrtf(var + 1e-5f);
    }
}

// ---------------------------------------------------------------------------
// Apply group norm + SiLU (vectorized float4)
// ---------------------------------------------------------------------------
__global__ __launch_bounds__(256) void gn_silu_kernel(
    const float* __restrict__ in, float* __restrict__ out,
    const float* __restrict__ gw, const float* __restrict__ gb)
{
    int i4 = blockIdx.x * 256 + threadIdx.x;
    if (i4 >= NTOT/4) return;
    size_t idx = (size_t)i4 * 4;
    int c = (int)((idx / HWP) % CC);
    int b = (int)(idx / ((size_t)CC * HWP));
    int bg = b * GG + c / CPG;
    float m = g_mean[bg], rs = g_rstd[bg];
    float sw = gw[c] * rs;
    float sb = gb[c] - m * sw;
    float4 v = *(const float4*)&in[idx];
    float y;
    y = fmaf(v.x, sw, sb); v.x = y * sigf(y);
    y = fmaf(v.y, sw, sb); v.y = y * sigf(y);
    y = fmaf(v.z, sw, sb); v.z = y * sigf(y);
    y = fmaf(v.w, sw, sb); v.w = y * sigf(y);
    *(float4*)&out[idx] = v;
}

// ---------------------------------------------------------------------------
// W-direction scans (lr forward + rl backward). One thread per (b,c,h) row.
// out = lr + rl
// ---------------------------------------------------------------------------
__global__ __launch_bounds__(256) void scanW_kernel(
    const float* __restrict__ xp, float* __restrict__ out,
    const float* __restrict__ a_p, const float* __restrict__ b_p,
    const float* __restrict__ c_p, const float* __restrict__ d_p)
{
    int r = blockIdx.x * 256 + threadIdx.x;
    if (r >= BB*CC*HH) return;
    int c = (r / HH) % CC;
    float a0 = sigf(a_p[c]),      b0 = b_p[c],      c0 = c_p[c],      d0 = d_p[c];
    float a1 = sigf(a_p[CC + c]), b1 = b_p[CC + c], c1 = c_p[CC + c], d1 = d_p[CC + c];
    size_t base = (size_t)r * WW;

    float h = 0.f;
    for (int i0 = 0; i0 < WW; i0 += 4) {
        float4 x = *(const float4*)&xp[base + i0];
        float4 y;
        h = fmaf(a0, h, b0 * x.x); y.x = fmaf(c0, h, d0 * x.x);
        h = fmaf(a0, h, b0 * x.y); y.y = fmaf(c0, h, d0 * x.y);
        h = fmaf(a0, h, b0 * x.z); y.z = fmaf(c0, h, d0 * x.z);
        h = fmaf(a0, h, b0 * x.w); y.w = fmaf(c0, h, d0 * x.w);
        *(float4*)&out[base + i0] = y;
    }
    h = 0.f;
    for (int i0 = WW - 4; i0 >= 0; i0 -= 4) {
        float4 x = *(const float4*)&xp[base + i0];
        float4 o = *(float4*)&out[base + i0];
        h = fmaf(a1, h, b1 * x.w); o.w += fmaf(c1, h, d1 * x.w);
        h = fmaf(a1, h, b1 * x.z); o.z += fmaf(c1, h, d1 * x.z);
        h = fmaf(a1, h, b1 * x.y); o.y += fmaf(c1, h, d1 * x.y);
        h = fmaf(a1, h, b1 * x.x); o.x += fmaf(c1, h, d1 * x.x);
        *(float4*)&out[base + i0] = o;
    }
}

// ---------------------------------------------------------------------------
// H-direction scans (tb forward + bt backward) + final combine with gate.
// One thread handles 4 adjacent columns (float4). acc holds lr+rl on entry;
// on exit acc = 0.25*(lr+rl+tb+bt)*gate.
// ---------------------------------------------------------------------------
__global__ __launch_bounds__(256) void scanH_kernel(
    const float* __restrict__ xp, const float* __restrict__ gate,
    float* __restrict__ acc,
    const float* __restrict__ a_p, const float* __restrict__ b_p,
    const float* __restrict__ c_p, const float* __restrict__ d_p)
{
    int t = blockIdx.x * 256 + threadIdx.x;
    if (t >= BB*CC*(WW/4)) return;
    int wq = t % (WW/4);
    int bc = t / (WW/4);
    int c  = bc % CC;
    float a2 = sigf(a_p[2*CC + c]), b2 = b_p[2*CC + c], c2 = c_p[2*CC + c], d2 = d_p[2*CC + c];
    float a3 = sigf(a_p[3*CC + c]), b3 = b_p[3*CC + c], c3 = c_p[3*CC + c], d3 = d_p[3*CC + c];
    size_t base = (size_t)bc * HWP + wq * 4;

    float4 h = make_float4(0.f, 0.f, 0.f, 0.f);
    for (int j = 0; j < HH; j++) {
        size_t off = base + (size_t)j * WW;
        float4 x = *(const float4*)&xp[off];
        float4 o = *(float4*)&acc[off];
        h.x = fmaf(a2, h.x, b2 * x.x); o.x += fmaf(c2, h.x, d2 * x.x);
        h.y = fmaf(a2, h.y, b2 * x.y); o.y += fmaf(c2, h.y, d2 * x.y);
        h.z = fmaf(a2, h.z, b2 * x.z); o.z += fmaf(c2, h.z, d2 * x.z);
        h.w = fmaf(a2, h.w, b2 * x.w); o.w += fmaf(c2, h.w, d2 * x.w);
        *(float4*)&acc[off] = o;
    }
    h = make_float4(0.f, 0.f, 0.f, 0.f);
    for (int j = HH - 1; j >= 0; j--) {
        size_t off = base + (size_t)j * WW;
        float4 x = *(const float4*)&xp[off];
        float4 o = *(float4*)&acc[off];
        float4 g = *(const float4*)&gate[off];
        h.x = fmaf(a3, h.x, b3 * x.x); o.x = 0.25f * (o.x + fmaf(c3, h.x, d3 * x.x)) * g.x;
        h.y = fmaf(a3, h.y, b3 * x.y); o.y = 0.25f * (o.y + fmaf(c3, h.y, d3 * x.y)) * g.y;
        h.z = fmaf(a3, h.z, b3 * x.z); o.z = 0.25f * (o.z + fmaf(c3, h.z, d3 * x.z)) * g.z;
        h.w = fmaf(a3, h.w, b3 * x.w); o.w = 0.25f * (o.w + fmaf(c3, h.w, d3 * x.w)) * g.w;
        *(float4*)&acc[off] = o;
    }
}

// ---------------------------------------------------------------------------
// Depthwise 3x3 conv, SAME zero padding. One thread per output pixel.
// ---------------------------------------------------------------------------
__global__ __launch_bounds__(256) void dw_kernel(
    const float* __restrict__ in, const float* __restrict__ wt,
    float* __restrict__ out)
{
    int idx = blockIdx.x * 256 + threadIdx.x;
    if (idx >= NTOT) return;
    int w = idx % WW;
    int h = (idx / WW) % HH;
    int c = (idx / HWP) % CC;
    const float* pk = wt + c * 9;
    float k0 = pk[0], k1 = pk[1], k2 = pk[2];
    float k3 = pk[3], k4 = pk[4], k5 = pk[5];
    float k6 = pk[6], k7 = pk[7], k8 = pk[8];
    const float* pl = in + (size_t)(idx / HWP) * HWP;
    float s = 0.f;
    if (h > 0) {
        const float* rr = pl + (size_t)(h-1) * WW;
        if (w > 0)    s = fmaf(rr[w-1], k0, s);
                      s = fmaf(rr[w],   k1, s);
        if (w < WW-1) s = fmaf(rr[w+1], k2, s);
    }
    {
        const float* rr = pl + (size_t)h * WW;
        if (w > 0)    s = fmaf(rr[w-1], k3, s);
                      s = fmaf(rr[w],   k4, s);
        if (w < WW-1) s = fmaf(rr[w+1], k5, s);
    }
    if (h < HH-1) {
        const float* rr = pl + (size_t)(h+1) * WW;
        if (w > 0)    s = fmaf(rr[w-1], k6, s);
                      s = fmaf(rr[w],   k7, s);
        if (w < WW-1) s = fmaf(rr[w+1], k8, s);
    }
    out[idx] = s;
}

// ---------------------------------------------------------------------------
extern "C" void kernel_launch(void* const* d_in, const int* in_sizes, int n_in,
                              void* d_out, int out_size)
{
    const float* x      = (const float*)d_in[0];
    const float* in_w   = (const float*)d_in[1];
    const float* gn1_w  = (const float*)d_in[2];
    const float* gn1_b  = (const float*)d_in[3];
    const float* a_p    = (const float*)d_in[4];
    const float* b_p    = (const float*)d_in[5];
    const float* c_p    = (const float*)d_in[6];
    const float* d_p    = (const float*)d_in[7];
    const float* gate_w = (const float*)d_in[8];
    const float* gate_b = (const float*)d_in[9];
    const float* dw_w   = (const float*)d_in[10];
    const float* pw_w   = (const float*)d_in[11];
    const float* gn2_w  = (const float*)d_in[12];
    const float* gn2_b  = (const float*)d_in[13];
    float* out = (float*)d_out;

    float *buf0, *buf1, *buf2;
    cudaGetSymbolAddress((void**)&buf0, g_buf0);
    cudaGetSymbolAddress((void**)&buf1, g_buf1);
    cudaGetSymbolAddress((void**)&buf2, g_buf2);

    dim3 ggrid(HWP/128, CC/128, BB);   // (72, 2, 16)
    int elem4_blocks = (NTOT/4 + 255) / 256;       // 36864
    int scanW_blocks = (BB*CC*HH + 255) / 256;     // 1536
    int scanH_blocks = (BB*CC*(WW/4) + 255) / 256; // 384
    int dw_blocks    = (NTOT + 255) / 256;         // 147456

    // 1. xp_raw = in_w @ x
    gemm_tc<0><<<ggrid, 256>>>(in_w, x, buf0, nullptr);
    // 2. gn1 stats
    stats_kernel<<<BB*GG, 256>>>(buf0);
    // 3. xp = silu(gn1(xp_raw))
    gn_silu_kernel<<<elem4_blocks, 256>>>(buf0, buf1, gn1_w, gn1_b);
    // 4. gate = sigmoid(gate_w @ xp + gate_b)
    gemm_tc<1><<<ggrid, 256>>>(gate_w, buf1, buf0, gate_b);
    // 5. buf2 = lr + rl
    scanW_kernel<<<scanW_blocks, 256>>>(buf1, buf2, a_p, b_p, c_p, d_p);
    // 6. buf2 = 0.25*(lr+rl+tb+bt)*gate
    scanH_kernel<<<scanH_blocks, 256>>>(buf1, buf0, buf2, a_p, b_p, c_p, d_p);
    // 7. depthwise 3x3
    dw_kernel<<<dw_blocks, 256>>>(buf2, dw_w, buf1);
    // 8. out_raw = pw_w @ dw
    gemm_tc<0><<<ggrid, 256>>>(pw_w, buf1, buf0, nullptr);
    // 9. gn2 stats
    stats_kernel<<<BB*GG, 256>>>(buf0);
    // 10. out = silu(gn2(out_raw))
    gn_silu_kernel<<<elem4_blocks, 256>>>(buf0, out, gn2_w, gn2_b);
}